// round 15
// baseline (speedup 1.0000x reference)
#include <cuda_runtime.h>
#include <cuda_fp16.h>
#include <cstdint>

// ============================================================================
// Problem constants
// ============================================================================
#define B_DIM 32768
#define H_DIM 512
#define KTOT  1024   // E + H
#define NTOT  2048   // 4*H

// GEMM tiling
#define BM 128
#define BN 128
#define BK 64              // halves per K-chunk
#define NKIT (KTOT / BK)   // 16
#define STAGES 4
#define ROWB 144           // 128B data + 16B pad per row (conflict-free ldmatrix)
#define TILE_BYTES (128 * ROWB)           // 18432
#define STAGE_BYTES (2 * TILE_BYTES)      // 36864
#define SMEM_TOTAL (STAGES * STAGE_BYTES) // 147456 -> 1 CTA/SM (occ-1 by design)
// epilogue: csm f32 (128 x 132 = 67584B) at 0; f16 park region above it
#define CSTRIDE 132
#define HREG_OFF 69632                    // 69632 + 128*272 = 104448 <= 147456
#define HREG_ROWB 272                     // 136 halves per row

#define NTHREADS 512       // 16 warps: kshalf(2) x warpN(4) x warpM(2), tile 64x32
                           // occ 1: 512 thr @ <=128 regs, 16 warps/SM = 4/SMSP

// convert grid split
#define A_BLOCKS ((B_DIM * KTOT) / 4 / 256)   // 32768
#define W_BLOCKS ((NTOT * KTOT) / 4 / 256)    // 2048

// ============================================================================
// Scratch (device globals — allocation-free)
// ============================================================================
__device__ __half g_A[(size_t)B_DIM * KTOT];   // 64 MB: [x | h0] fp16
__device__ __half g_W[(size_t)NTOT * KTOT];    // 4 MB: gate-interleaved [W_x | W_h]
__device__ float  g_bias[NTOT];                // b_x + b_h, gate-interleaved

// ============================================================================
// PTX helpers (compute_103-safe: legacy mma + Ampere mbarrier/cp.async)
// ============================================================================
__device__ __forceinline__ uint32_t smem_u32(const void* p) {
    uint32_t a;
    asm("{ .reg .u64 t; cvta.to.shared.u64 t, %1; cvt.u32.u64 %0, t; }" : "=r"(a) : "l"(p));
    return a;
}

__device__ __forceinline__ void cp16(uint32_t saddr, const void* gaddr) {
    asm volatile("cp.async.cg.shared.global [%0], [%1], 16;" :: "r"(saddr), "l"(gaddr) : "memory");
}

#define MBARRIER_INIT(addr, cnt) \
    asm volatile("mbarrier.init.shared.b64 [%0], %1;" :: "r"((uint32_t)(addr)), "r"((uint32_t)(cnt)) : "memory")

#define MBARRIER_ARRIVE(addr) \
    asm volatile("mbarrier.arrive.shared.b64 _, [%0];" :: "r"((uint32_t)(addr)) : "memory")

#define CP_ASYNC_MBAR_ARRIVE(addr) \
    asm volatile("cp.async.mbarrier.arrive.noinc.shared.b64 [%0];" :: "r"((uint32_t)(addr)) : "memory")

#define MBAR_WAIT(addr, parity) do {                                            \
    uint32_t _m = (uint32_t)(addr);                                             \
    uint32_t _p = (uint32_t)(parity);                                           \
    uint32_t _done;                                                             \
    asm volatile("{\n\t.reg .pred p;\n\t"                                       \
        "mbarrier.try_wait.parity.shared.b64 p, [%1], %2;\n\t"                  \
        "selp.b32 %0, 1, 0, p;\n\t}"                                            \
        : "=r"(_done) : "r"(_m), "r"(_p) : "memory");                           \
    if (!_done) {                                                               \
        asm volatile("{\n\t.reg .pred P1;\n\t"                                  \
            "WL_%=:\n\t"                                                        \
            "mbarrier.try_wait.parity.shared.b64 P1, [%0], %1;\n\t"             \
            "@P1 bra.uni WD_%=;\n\t"                                            \
            "bra.uni WL_%=;\n\t"                                                \
            "WD_%=:\n\t}"                                                       \
            :: "r"(_m), "r"(_p) : "memory");                                    \
    }                                                                           \
} while (0)

__device__ __forceinline__ void ldsm_x4(uint32_t& r0, uint32_t& r1, uint32_t& r2, uint32_t& r3,
                                        uint32_t addr) {
    asm volatile("ldmatrix.sync.aligned.m8n8.x4.shared.b16 {%0,%1,%2,%3}, [%4];"
                 : "=r"(r0), "=r"(r1), "=r"(r2), "=r"(r3) : "r"(addr));
}

// f16-accumulate mma (rt ~8/SMSP confirmed by R8-R13 profiles)
__device__ __forceinline__ void mma16816_f16(uint32_t& d0, uint32_t& d1,
                                             uint32_t a0, uint32_t a1, uint32_t a2, uint32_t a3,
                                             uint32_t b0, uint32_t b1) {
    asm volatile("mma.sync.aligned.m16n8k16.row.col.f16.f16.f16.f16 "
                 "{%0,%1}, {%2,%3,%4,%5}, {%6,%7}, {%0,%1};"
                 : "+r"(d0), "+r"(d1)
                 : "r"(a0), "r"(a1), "r"(a2), "r"(a3), "r"(b0), "r"(b1));
}

// ============================================================================
// Merged convert pass: A = [x|h0] -> fp16 ; W gate-interleaved -> fp16 ; bias
// ============================================================================
__global__ __launch_bounds__(256) void convert_all_kernel(
        const float* __restrict__ x,  const float* __restrict__ h0,
        const float* __restrict__ Wx, const float* __restrict__ Wh,
        const float* __restrict__ bx, const float* __restrict__ bh) {
    if (blockIdx.x < A_BLOCKS) {
        int g = blockIdx.x * 256 + threadIdx.x;   // group of 4 elements
        int b = g >> 8;
        int cg = g & 255;
        const float* src = (cg < 128) ? (x + b * 512 + cg * 4)
                                      : (h0 + b * 512 + (cg - 128) * 4);
        float4 v = *reinterpret_cast<const float4*>(src);
        __half2 lo = __floats2half2_rn(v.x, v.y);
        __half2 hi = __floats2half2_rn(v.z, v.w);
        uint2 u;
        u.x = *reinterpret_cast<const unsigned*>(&lo);
        u.y = *reinterpret_cast<const unsigned*>(&hi);
        *reinterpret_cast<uint2*>(g_A + (size_t)g * 4) = u;
    } else {
        int g = (blockIdx.x - A_BLOCKS) * 256 + threadIdx.x;
        int r = g >> 8;           // dest row = h*4 + k
        int cg = g & 255;
        int k = r & 3;
        int h = r >> 2;
        int c = cg * 4;
        const float* src = (cg < 128) ? (Wx + (k * 512 + h) * 512 + c)
                                      : (Wh + (k * 512 + h) * 512 + (c - 512));
        float4 v = *reinterpret_cast<const float4*>(src);
        __half2 lo = __floats2half2_rn(v.x, v.y);
        __half2 hi = __floats2half2_rn(v.z, v.w);
        uint2 u;
        u.x = *reinterpret_cast<const unsigned*>(&lo);
        u.y = *reinterpret_cast<const unsigned*>(&hi);
        *reinterpret_cast<uint2*>(g_W + (size_t)g * 4) = u;

        if (blockIdx.x == A_BLOCKS) {
            for (int rr = threadIdx.x; rr < NTOT; rr += 256) {
                int kk = rr & 3, hh = rr >> 2;
                g_bias[rr] = bx[kk * 512 + hh] + bh[kk * 512 + hh];
            }
        }
    }
}

// ============================================================================
// Fused GEMM: 16-warp CTA (512 thr, occ 1), 4-stage ring, warp tile 64x32,
// intra-stage split-K (kshalf 0 -> ks{0,1}, kshalf 1 -> ks{2,3}), single
// f16 acc (32 regs, K=512/warp), fp32 combine once in epilogue.
// ============================================================================
__device__ __forceinline__ void stage_tile(uint32_t sb, int buf, int m0, int n0, int k0, int tid) {
    const uint32_t abase = sb + buf * STAGE_BYTES;
    const uint32_t bbase = abase + TILE_BYTES;
#pragma unroll
    for (int j = 0; j < 2; j++) {
        int i = tid + j * NTHREADS;   // 0..1023 16B-chunk slot (128 rows x 8 chunks)
        int row = i >> 3;
        int c8 = i & 7;
        uint32_t dst_off = (uint32_t)(row * ROWB + c8 * 16);
        cp16(abase + dst_off, g_A + (size_t)(m0 + row) * KTOT + k0 + c8 * 8);
        cp16(bbase + dst_off, g_W + (size_t)(n0 + row) * KTOT + k0 + c8 * 8);
    }
}

__global__ __launch_bounds__(NTHREADS, 1) void lstm_gemm_kernel(const float* __restrict__ c0,
                                                                float* __restrict__ out) {
    extern __shared__ char smem[];
    __shared__ uint64_t s_mbar[2 * STAGES];   // [full 0..3 | empty 0..3]
    const uint32_t sb = smem_u32(smem);
    const uint32_t mb = smem_u32(s_mbar);
    const int tid = threadIdx.x;
    const int wid = tid >> 5;
    const int lane = tid & 31;
    const int n0 = blockIdx.x * BN;   // N fastest -> CTAs sharing A run together
    const int m0 = blockIdx.y * BM;

    const int kshalf = wid >> 3;      // 0: ks {0,1}, 1: ks {2,3}
    const int warpN = (wid >> 1) & 3; // 4 N-warps of 32 cols
    const int warpM = wid & 1;        // 2 M-warps of 64 rows

    if (tid == 0) {
#pragma unroll
        for (int s = 0; s < STAGES; s++) {
            MBARRIER_INIT(mb + 8 * s, NTHREADS);               // full[s]
            MBARRIER_INIT(mb + 8 * (STAGES + s), NTHREADS);    // empty[s]
        }
    }
    __syncthreads();

    // ldmatrix per-lane base offsets, including this group's ks base (32B per ks)
    const uint32_t ks_base = (uint32_t)(kshalf * 2 * 32);
    const uint32_t a_lane_off = (uint32_t)((warpM * 64 + (lane & 15)) * ROWB
                                           + ((lane >> 4) & 1) * 16) + ks_base;
    const uint32_t b_lane_off = (uint32_t)((warpN * 32 + (lane & 7) + ((lane >> 4) & 1) * 8) * ROWB
                                           + ((lane >> 3) & 1) * 16) + ks_base;

    int pstage = 0, pphase = 1;       // producer (phase 1 -> first empty-waits pass)
    int cstage = 0, cphase = 0;       // consumer (in-order, every stage)

    // Prologue: fill stages 0..2
#pragma unroll
    for (int f = 0; f < STAGES - 1; f++) {
        MBAR_WAIT(mb + 8 * (STAGES + pstage), pphase);
        stage_tile(sb, pstage, m0, n0, f * BK, tid);
        CP_ASYNC_MBAR_ARRIVE(mb + 8 * pstage);
        if (++pstage == STAGES) { pstage = 0; pphase ^= 1; }
    }

    // Single f16 accumulator set: warp tile 64x32 -> [mt 16rows][nt 8cols][2] = 32 regs
    uint32_t acc[4][4][2];
#pragma unroll
    for (int mt = 0; mt < 4; mt++)
#pragma unroll
        for (int nt = 0; nt < 4; nt++) { acc[mt][nt][0] = 0u; acc[mt][nt][1] = 0u; }

#pragma unroll 1
    for (int kt = 0; kt < NKIT; kt++) {
        // Produce stage kt+STAGES-1 (all warps)
        if (kt + STAGES - 1 < NKIT) {
            MBAR_WAIT(mb + 8 * (STAGES + pstage), pphase);
            stage_tile(sb, pstage, m0, n0, (kt + STAGES - 1) * BK, tid);
            CP_ASYNC_MBAR_ARRIVE(mb + 8 * pstage);
            if (++pstage == STAGES) { pstage = 0; pphase ^= 1; }
        }

        // Consume stage kt: this group's two ks-subchunks
        MBAR_WAIT(mb + 8 * cstage, cphase);
        const uint32_t abase = sb + cstage * STAGE_BYTES;
        const uint32_t bbase = abase + TILE_BYTES;
#pragma unroll
        for (int ks = 0; ks < 2; ks++) {
            uint32_t a[4][4];
#pragma unroll
            for (int mt = 0; mt < 4; mt++)
                ldsm_x4(a[mt][0], a[mt][1], a[mt][2], a[mt][3],
                        abase + a_lane_off + (uint32_t)(mt * 16 * ROWB)
                              + (uint32_t)(ks * 32));
            uint32_t b[4][2];
#pragma unroll
            for (int ntp = 0; ntp < 2; ntp++) {
                uint32_t r0, r1, r2, r3;
                ldsm_x4(r0, r1, r2, r3,
                        bbase + b_lane_off + (uint32_t)(ntp * 16 * ROWB)
                              + (uint32_t)(ks * 32));
                b[2 * ntp + 0][0] = r0; b[2 * ntp + 0][1] = r1;
                b[2 * ntp + 1][0] = r2; b[2 * ntp + 1][1] = r3;
            }
#pragma unroll
            for (int mt = 0; mt < 4; mt++)
#pragma unroll
                for (int nt = 0; nt < 4; nt++)
                    mma16816_f16(acc[mt][nt][0], acc[mt][nt][1],
                                 a[mt][0], a[mt][1], a[mt][2], a[mt][3],
                                 b[nt][0], b[nt][1]);
        }
        MBARRIER_ARRIVE(mb + 8 * (STAGES + cstage));
        if (++cstage == STAGES) { cstage = 0; cphase ^= 1; }
    }

    // -------- Epilogue --------
    __syncthreads();   // all consumption done; stage buffers reusable

    // Phase 1: kshalf-1 warps park f16 accs in smem (they cover the full 128x128)
    const int rbase = warpM * 64 + (lane >> 2);
    const int cbase = warpN * 32 + 2 * (lane & 3);
    if (kshalf == 1) {
#pragma unroll
        for (int mt = 0; mt < 4; mt++)
#pragma unroll
            for (int nt = 0; nt < 4; nt++) {
                int r = rbase + mt * 16;
                int c = cbase + nt * 8;
                *reinterpret_cast<uint32_t*>(smem + HREG_OFF + r * HREG_ROWB + c * 2) = acc[mt][nt][0];
                *reinterpret_cast<uint32_t*>(smem + HREG_OFF + (r + 8) * HREG_ROWB + c * 2) = acc[mt][nt][1];
            }
    }
    __syncthreads();

    // Phase 2: kshalf-0 warps promote own + partner to fp32, stage into csm
    float* csm = reinterpret_cast<float*>(smem);
    if (kshalf == 0) {
#pragma unroll
        for (int mt = 0; mt < 4; mt++)
#pragma unroll
            for (int nt = 0; nt < 4; nt++) {
                int r = rbase + mt * 16;
                int c = cbase + nt * 8;
                uint32_t p0 = *reinterpret_cast<uint32_t*>(smem + HREG_OFF + r * HREG_ROWB + c * 2);
                uint32_t p1 = *reinterpret_cast<uint32_t*>(smem + HREG_OFF + (r + 8) * HREG_ROWB + c * 2);
                float2 o0 = __half22float2(*reinterpret_cast<__half2*>(&acc[mt][nt][0]));
                float2 o1 = __half22float2(*reinterpret_cast<__half2*>(&acc[mt][nt][1]));
                float2 q0 = __half22float2(*reinterpret_cast<__half2*>(&p0));
                float2 q1 = __half22float2(*reinterpret_cast<__half2*>(&p1));
                *reinterpret_cast<float2*>(csm + r * CSTRIDE + c) =
                    make_float2(o0.x + q0.x, o0.y + q0.y);
                *reinterpret_cast<float2*>(csm + (r + 8) * CSTRIDE + c) =
                    make_float2(o1.x + q1.x, o1.y + q1.y);
            }
    }
    __syncthreads();

    // Phase 3: fused LSTM gates, fully coalesced outputs
    {
        const int hbase = n0 >> 2;                  // 32 hidden units per CTA tile
        const int h = hbase + lane;
        float4 bias = *reinterpret_cast<const float4*>(g_bias + n0 + lane * 4);
#pragma unroll 4
        for (int it = 0; it < 8; it++) {
            int row = wid + 16 * it;                // 16 warps x 8 iters = 128 rows
            int b = m0 + row;
            float4 z = *reinterpret_cast<const float4*>(csm + row * CSTRIDE + lane * 4);
            float zi = z.x + bias.x;
            float zf = z.y + bias.y;
            float zo = z.z + bias.z;
            float zg = z.w + bias.w;
            float ig = 1.0f / (1.0f + __expf(-zi));
            float fg = 1.0f / (1.0f + __expf(-zf));
            float og = 1.0f / (1.0f + __expf(-zo));
            float gg = tanhf(zg);
            float c1 = fg * __ldg(c0 + (size_t)b * H_DIM + h) + ig * gg;
            float h1 = og * tanhf(c1);
            out[(size_t)b * H_DIM + h] = h1;                                  // h1
            out[(size_t)B_DIM * H_DIM + (size_t)b * H_DIM + h] = c1;          // c1
        }
    }
}

// ============================================================================
// kernel_launch
// ============================================================================
extern "C" void kernel_launch(void* const* d_in, const int* in_sizes, int n_in,
                              void* d_out, int out_size) {
    (void)in_sizes; (void)n_in; (void)out_size;
    const float* x  = (const float*)d_in[0];
    const float* h0 = (const float*)d_in[1];
    const float* c0 = (const float*)d_in[2];
    const float* Wx = (const float*)d_in[3];
    const float* bx = (const float*)d_in[4];
    const float* Wh = (const float*)d_in[5];
    const float* bh = (const float*)d_in[6];
    float* out = (float*)d_out;

    convert_all_kernel<<<A_BLOCKS + W_BLOCKS, 256>>>(x, h0, Wx, Wh, bx, bh);

    cudaFuncSetAttribute(lstm_gemm_kernel, cudaFuncAttributeMaxDynamicSharedMemorySize, SMEM_TOTAL);
    dim3 grid(NTOT / BN, B_DIM / BM);   // (16, 256), N fastest
    lstm_gemm_kernel<<<grid, NTHREADS, SMEM_TOTAL>>>(c0, out);
}

// round 16
// speedup vs baseline: 1.4650x; 1.4650x over previous
#include <cuda_runtime.h>
#include <cuda_fp16.h>
#include <cstdint>

// ============================================================================
// Problem constants
// ============================================================================
#define B_DIM 32768
#define H_DIM 512
#define KTOT  1024   // E + H
#define NTOT  2048   // 4*H

// GEMM tiling (R10 config: best measured, 430.9us)
#define BM 128
#define BN 128
#define BK 64              // halves per K-chunk
#define NKIT (KTOT / BK)   // 16
#define STAGES 3
#define ROWB 144           // 128B data + 16B pad per row (conflict-free ldmatrix)
#define TILE_BYTES (128 * ROWB)           // 18432
#define STAGE_BYTES (2 * TILE_BYTES)      // 36864
#define SMEM_TOTAL (STAGES * STAGE_BYTES) // 110592 -> 2 CTA/SM
// epilogue C stage: 128 rows x 132 floats
#define CSTRIDE 132

#define NTHREADS 256       // 8 warps: 2(M) x 4(N), warp tile 64x32, occ 2

// convert grid split
#define A_BLOCKS ((B_DIM * KTOT) / 4 / 256)   // 32768
#define W_BLOCKS ((NTOT * KTOT) / 4 / 256)    // 2048

// ============================================================================
// Scratch (device globals — allocation-free)
// ============================================================================
__device__ __half g_A[(size_t)B_DIM * KTOT];   // 64 MB: [x | h0] fp16
__device__ __half g_W[(size_t)NTOT * KTOT];    // 4 MB: gate-interleaved [W_x | W_h]
__device__ float  g_bias[NTOT];                // b_x + b_h, gate-interleaved

// ============================================================================
// PTX helpers (compute_103-safe: legacy mma + Ampere mbarrier/cp.async)
// ============================================================================
__device__ __forceinline__ uint32_t smem_u32(const void* p) {
    uint32_t a;
    asm("{ .reg .u64 t; cvta.to.shared.u64 t, %1; cvt.u32.u64 %0, t; }" : "=r"(a) : "l"(p));
    return a;
}

__device__ __forceinline__ void cp16(uint32_t saddr, const void* gaddr) {
    asm volatile("cp.async.cg.shared.global [%0], [%1], 16;" :: "r"(saddr), "l"(gaddr) : "memory");
}

#define MBARRIER_INIT(addr, cnt) \
    asm volatile("mbarrier.init.shared.b64 [%0], %1;" :: "r"((uint32_t)(addr)), "r"((uint32_t)(cnt)) : "memory")

#define MBARRIER_ARRIVE(addr) \
    asm volatile("mbarrier.arrive.shared.b64 _, [%0];" :: "r"((uint32_t)(addr)) : "memory")

#define CP_ASYNC_MBAR_ARRIVE(addr) \
    asm volatile("cp.async.mbarrier.arrive.noinc.shared.b64 [%0];" :: "r"((uint32_t)(addr)) : "memory")

// try_wait with HW-sleep hint: spinning warps stop stealing issue slots
#define MBAR_WAIT(addr, parity) do {                                                    \
    uint32_t _m = (uint32_t)(addr);                                                     \
    uint32_t _p = (uint32_t)(parity);                                                   \
    uint32_t _done;                                                                     \
    asm volatile("{\n\t.reg .pred p;\n\t"                                               \
        "mbarrier.try_wait.parity.shared.b64 p, [%1], %2;\n\t"                          \
        "selp.b32 %0, 1, 0, p;\n\t}"                                                    \
        : "=r"(_done) : "r"(_m), "r"(_p) : "memory");                                   \
    if (!_done) {                                                                       \
        asm volatile("{\n\t.reg .pred P1;\n\t"                                          \
            "WL_%=:\n\t"                                                                \
            "mbarrier.try_wait.parity.shared.b64 P1, [%0], %1, 0x989680;\n\t"           \
            "@P1 bra.uni WD_%=;\n\t"                                                    \
            "bra.uni WL_%=;\n\t"                                                        \
            "WD_%=:\n\t}"                                                               \
            :: "r"(_m), "r"(_p) : "memory");                                            \
    }                                                                                   \
} while (0)

__device__ __forceinline__ void ldsm_x4(uint32_t& r0, uint32_t& r1, uint32_t& r2, uint32_t& r3,
                                        uint32_t addr) {
    asm volatile("ldmatrix.sync.aligned.m8n8.x4.shared.b16 {%0,%1,%2,%3}, [%4];"
                 : "=r"(r0), "=r"(r1), "=r"(r2), "=r"(r3) : "r"(addr));
}

// f16-accumulate mma (rt ~8/SMSP confirmed by R8-R15 profiles)
__device__ __forceinline__ void mma16816_f16(uint32_t& d0, uint32_t& d1,
                                             uint32_t a0, uint32_t a1, uint32_t a2, uint32_t a3,
                                             uint32_t b0, uint32_t b1) {
    asm volatile("mma.sync.aligned.m16n8k16.row.col.f16.f16.f16.f16 "
                 "{%0,%1}, {%2,%3,%4,%5}, {%6,%7}, {%0,%1};"
                 : "+r"(d0), "+r"(d1)
                 : "r"(a0), "r"(a1), "r"(a2), "r"(a3), "r"(b0), "r"(b1));
}

// ============================================================================
// Merged convert pass: A = [x|h0] -> fp16 ; W gate-interleaved -> fp16 ; bias
// ============================================================================
__global__ __launch_bounds__(256) void convert_all_kernel(
        const float* __restrict__ x,  const float* __restrict__ h0,
        const float* __restrict__ Wx, const float* __restrict__ Wh,
        const float* __restrict__ bx, const float* __restrict__ bh) {
    if (blockIdx.x < A_BLOCKS) {
        int g = blockIdx.x * 256 + threadIdx.x;   // group of 4 elements
        int b = g >> 8;
        int cg = g & 255;
        const float* src = (cg < 128) ? (x + b * 512 + cg * 4)
                                      : (h0 + b * 512 + (cg - 128) * 4);
        float4 v = *reinterpret_cast<const float4*>(src);
        __half2 lo = __floats2half2_rn(v.x, v.y);
        __half2 hi = __floats2half2_rn(v.z, v.w);
        uint2 u;
        u.x = *reinterpret_cast<const unsigned*>(&lo);
        u.y = *reinterpret_cast<const unsigned*>(&hi);
        *reinterpret_cast<uint2*>(g_A + (size_t)g * 4) = u;
    } else {
        int g = (blockIdx.x - A_BLOCKS) * 256 + threadIdx.x;
        int r = g >> 8;           // dest row = h*4 + k
        int cg = g & 255;
        int k = r & 3;
        int h = r >> 2;
        int c = cg * 4;
        const float* src = (cg < 128) ? (Wx + (k * 512 + h) * 512 + c)
                                      : (Wh + (k * 512 + h) * 512 + (c - 512));
        float4 v = *reinterpret_cast<const float4*>(src);
        __half2 lo = __floats2half2_rn(v.x, v.y);
        __half2 hi = __floats2half2_rn(v.z, v.w);
        uint2 u;
        u.x = *reinterpret_cast<const unsigned*>(&lo);
        u.y = *reinterpret_cast<const unsigned*>(&hi);
        *reinterpret_cast<uint2*>(g_W + (size_t)g * 4) = u;

        if (blockIdx.x == A_BLOCKS) {
            for (int rr = threadIdx.x; rr < NTOT; rr += 256) {
                int kk = rr & 3, hh = rr >> 2;
                g_bias[rr] = bx[kk * 512 + hh] + bh[kk * 512 + hh];
            }
        }
    }
}

// ============================================================================
// Fused GEMM (R10 structure + produce-inside-consume + hoisted pointers)
//   CTA 128x128, 8 warps = 2(M) x 4(N), warp tile 64x32, occ 2
//   dual f16 acc: dlo (kt 0..7), dhi (kt 8..15); fp32 combine once
// ============================================================================

// consume two ks-subchunks [KS0, KS0+1] of the stage at (abase,bbase) into ACC
#define CONSUME_HALF(ACC, KS0)                                                    \
    do {                                                                          \
        _Pragma("unroll")                                                         \
        for (int ks = (KS0); ks < (KS0) + 2; ks++) {                              \
            uint32_t a[4][4];                                                     \
            _Pragma("unroll")                                                     \
            for (int mt = 0; mt < 4; mt++)                                        \
                ldsm_x4(a[mt][0], a[mt][1], a[mt][2], a[mt][3],                   \
                        abase + a_lane_off + (uint32_t)(mt * 16 * ROWB)           \
                              + (uint32_t)(ks * 32));                             \
            uint32_t b[4][2];                                                     \
            _Pragma("unroll")                                                     \
            for (int ntp = 0; ntp < 2; ntp++) {                                   \
                uint32_t r0, r1, r2, r3;                                          \
                ldsm_x4(r0, r1, r2, r3,                                           \
                        bbase + b_lane_off + (uint32_t)(ntp * 16 * ROWB)          \
                              + (uint32_t)(ks * 32));                             \
                b[2 * ntp + 0][0] = r0; b[2 * ntp + 0][1] = r1;                   \
                b[2 * ntp + 1][0] = r2; b[2 * ntp + 1][1] = r3;                   \
            }                                                                     \
            _Pragma("unroll")                                                     \
            for (int mt = 0; mt < 4; mt++)                                        \
                _Pragma("unroll")                                                 \
                for (int nt = 0; nt < 4; nt++)                                    \
                    mma16816_f16(ACC[mt][nt][0], ACC[mt][nt][1],                  \
                                 a[mt][0], a[mt][1], a[mt][2], a[mt][3],          \
                                 b[nt][0], b[nt][1]);                             \
        }                                                                         \
    } while (0)

// produce stage pstage from hoisted pointers at K offset k0 (halves)
#define PRODUCE_STAGE(K0)                                                         \
    do {                                                                          \
        MBAR_WAIT(mb + 8 * (STAGES + pstage), pphase);                            \
        uint32_t ab = sb + pstage * STAGE_BYTES + doff;                           \
        _Pragma("unroll")                                                         \
        for (int j = 0; j < 4; j++) {                                             \
            cp16(ab + (uint32_t)(j * 32 * ROWB), srcA0 + (K0) + j * 32 * KTOT);   \
            cp16(ab + (uint32_t)(TILE_BYTES + j * 32 * ROWB),                     \
                 srcW0 + (K0) + j * 32 * KTOT);                                   \
        }                                                                         \
        CP_ASYNC_MBAR_ARRIVE(mb + 8 * pstage);                                    \
        if (++pstage == STAGES) { pstage = 0; pphase ^= 1; }                      \
    } while (0)

// full k-iteration: wait, mma ks{0,1}, produce kt+2 (hidden), mma ks{2,3}, free
#define K_ITER(ACC, KT)                                                           \
    do {                                                                          \
        MBAR_WAIT(mb + 8 * cstage, cphase);                                       \
        const uint32_t abase = sb + cstage * STAGE_BYTES;                         \
        const uint32_t bbase = abase + TILE_BYTES;                                \
        CONSUME_HALF(ACC, 0);                                                     \
        if ((KT) + 2 < NKIT) PRODUCE_STAGE(((KT) + 2) * BK);                      \
        CONSUME_HALF(ACC, 2);                                                     \
        MBARRIER_ARRIVE(mb + 8 * (STAGES + cstage));                              \
        if (++cstage == STAGES) { cstage = 0; cphase ^= 1; }                      \
    } while (0)

__global__ __launch_bounds__(NTHREADS, 2) void lstm_gemm_kernel(const float* __restrict__ c0,
                                                                float* __restrict__ out) {
    extern __shared__ char smem[];
    __shared__ uint64_t s_mbar[2 * STAGES];   // [full 0..2 | empty 0..2]
    const uint32_t sb = smem_u32(smem);
    const uint32_t mb = smem_u32(s_mbar);
    const int tid = threadIdx.x;
    const int wid = tid >> 5;
    const int lane = tid & 31;
    const int n0 = blockIdx.x * BN;   // N fastest -> CTAs sharing A run together
    const int m0 = blockIdx.y * BM;

    const int warpM = wid & 1;        // 2 M-warps of 64 rows
    const int warpN = wid >> 1;       // 4 N-warps of 32 cols

    if (tid == 0) {
#pragma unroll
        for (int s = 0; s < STAGES; s++) {
            MBARRIER_INIT(mb + 8 * s, NTHREADS);               // full[s]
            MBARRIER_INIT(mb + 8 * (STAGES + s), NTHREADS);    // empty[s]
        }
    }
    __syncthreads();

    // hoisted producer addressing (src pointers invariant up to +k0)
    const uint32_t doff = (uint32_t)((tid >> 3) * ROWB + (tid & 7) * 16);
    const __half* srcA0 = g_A + (size_t)(m0 + (tid >> 3)) * KTOT + (tid & 7) * 8;
    const __half* srcW0 = g_W + (size_t)(n0 + (tid >> 3)) * KTOT + (tid & 7) * 8;

    // ldmatrix per-lane base offsets (within a stage buffer)
    const uint32_t a_lane_off = (uint32_t)((warpM * 64 + (lane & 15)) * ROWB + ((lane >> 4) & 1) * 16);
    const uint32_t b_lane_off = (uint32_t)((warpN * 32 + (lane & 7) + ((lane >> 4) & 1) * 8) * ROWB
                                           + ((lane >> 3) & 1) * 16);

    int pstage = 0, pphase = 1;  // producer (phase 1 -> first empty-waits pass)
    int cstage = 0, cphase = 0;  // consumer

    // Prologue: fill stages 0,1
    PRODUCE_STAGE(0 * BK);
    PRODUCE_STAGE(1 * BK);

    // Dual f16 accumulator sets (K=512 each; validated rel_err 5.9e-4)
    uint32_t dlo[4][4][2], dhi[4][4][2];
#pragma unroll
    for (int mt = 0; mt < 4; mt++)
#pragma unroll
        for (int nt = 0; nt < 4; nt++) {
            dlo[mt][nt][0] = 0u; dlo[mt][nt][1] = 0u;
            dhi[mt][nt][0] = 0u; dhi[mt][nt][1] = 0u;
        }

#pragma unroll 1
    for (int kt = 0; kt < NKIT / 2; kt++) {
        K_ITER(dlo, kt);
    }
#pragma unroll 1
    for (int kt = NKIT / 2; kt < NKIT; kt++) {
        K_ITER(dhi, kt);
    }

    // -------- Epilogue: promote f16 halves -> fp32, stage through smem --------
    __syncthreads();   // all warps done with stage buffers before reuse as csm
    float* csm = reinterpret_cast<float*>(smem);
    {
        const int rbase = warpM * 64 + (lane >> 2);
        const int cbase = warpN * 32 + 2 * (lane & 3);
#pragma unroll
        for (int mt = 0; mt < 4; mt++) {
#pragma unroll
            for (int nt = 0; nt < 4; nt++) {
                float2 l0 = __half22float2(*reinterpret_cast<__half2*>(&dlo[mt][nt][0]));
                float2 l1 = __half22float2(*reinterpret_cast<__half2*>(&dlo[mt][nt][1]));
                float2 h0v = __half22float2(*reinterpret_cast<__half2*>(&dhi[mt][nt][0]));
                float2 h1v = __half22float2(*reinterpret_cast<__half2*>(&dhi[mt][nt][1]));
                int r = rbase + mt * 16;
                int c = cbase + nt * 8;
                *reinterpret_cast<float2*>(csm + r * CSTRIDE + c) =
                    make_float2(l0.x + h0v.x, l0.y + h0v.y);
                *reinterpret_cast<float2*>(csm + (r + 8) * CSTRIDE + c) =
                    make_float2(l1.x + h1v.x, l1.y + h1v.y);
            }
        }
    }
    __syncthreads();

    {
        const int hbase = n0 >> 2;                  // 32 hidden units per CTA tile
        const int h = hbase + lane;
        float4 bias = *reinterpret_cast<const float4*>(g_bias + n0 + lane * 4);
#pragma unroll 4
        for (int it = 0; it < 16; it++) {
            int row = wid + 8 * it;                 // 8 warps x 16 iters = 128 rows
            int b = m0 + row;
            float4 z = *reinterpret_cast<const float4*>(csm + row * CSTRIDE + lane * 4);
            float zi = z.x + bias.x;
            float zf = z.y + bias.y;
            float zo = z.z + bias.z;
            float zg = z.w + bias.w;
            float ig = 1.0f / (1.0f + __expf(-zi));
            float fg = 1.0f / (1.0f + __expf(-zf));
            float og = 1.0f / (1.0f + __expf(-zo));
            float gg = tanhf(zg);
            float c1 = fg * __ldg(c0 + (size_t)b * H_DIM + h) + ig * gg;
            float h1 = og * tanhf(c1);
            out[(size_t)b * H_DIM + h] = h1;                                  // h1
            out[(size_t)B_DIM * H_DIM + (size_t)b * H_DIM + h] = c1;          // c1
        }
    }
}

// ============================================================================
// kernel_launch
// ============================================================================
extern "C" void kernel_launch(void* const* d_in, const int* in_sizes, int n_in,
                              void* d_out, int out_size) {
    (void)in_sizes; (void)n_in; (void)out_size;
    const float* x  = (const float*)d_in[0];
    const float* h0 = (const float*)d_in[1];
    const float* c0 = (const float*)d_in[2];
    const float* Wx = (const float*)d_in[3];
    const float* bx = (const float*)d_in[4];
    const float* Wh = (const float*)d_in[5];
    const float* bh = (const float*)d_in[6];
    float* out = (float*)d_out;

    convert_all_kernel<<<A_BLOCKS + W_BLOCKS, 256>>>(x, h0, Wx, Wh, bx, bh);

    cudaFuncSetAttribute(lstm_gemm_kernel, cudaFuncAttributeMaxDynamicSharedMemorySize, SMEM_TOTAL);
    dim3 grid(NTOT / BN, B_DIM / BM);   // (16, 256), N fastest
    lstm_gemm_kernel<<<grid, NTHREADS, SMEM_TOTAL>>>(c0, out);
}